// round 9
// baseline (speedup 1.0000x reference)
#include <cuda_runtime.h>
#include <stdint.h>
#include <stddef.h>

// ---------------- problem constants ----------------
#define NT      512
#define NG      32
#define DEPTH   8
#define NB      128
#define NTIME   4096
#define NF      64

#define H0 77
#define K0 141
#define KP0 148
#define KA0 76
#define KB0 72
#define H1 51
#define KP1 132
#define H2 128
#define KP2 180
#define H2H 64
#define RKC 32            // register-cached k floats per unit

// ---- shared memory layout (bytes) ----
// [0,512)    : mbarriers  A[s]=s*8, B[s]=64+s*8, C[s]=128+s*8
//   rank0: A=empty01 (cnt1)
//   rank1: A=full01 (cnt308), B=empty12 (cnt2)
//   rank2/3: A=full12 (cnt204), B=fullP (cnt256), C=emptyP (cnt1)
// [512,15872): rings
//   rank1: ring01 = DEPTH * 320 floats at byte 512
//   rank2/3: ring12 = DEPTH * 224 floats at 512; ringPeer = DEPTH * 256 floats at 7680
// [15872,..) : stage area
#define MBA(s)   ((s) * 8)
#define MBB(s)   (64 + (s) * 8)
#define MBC(s)   (128 + (s) * 8)
#define RING_BYTE      512
#define RINGP_BYTE     (512 + DEPTH * 224 * 4)   // 7680
#define STAGE_F        3968                       // float index of stage area
#define STAGE_MAXF     49152
#define SMEM_BYTES     (15872 + STAGE_MAXF * 4)   // 212480

struct Params {
    const float* x;
    const float* h0;
    const float* m[3];
    const float* W1[3]; const float* W2[3]; const float* Wa[3]; const float* Wb[3];
    const float* b1[3]; const float* b2[3]; const float* ba[3]; const float* bb[3];
    float* out;
    int out_size;
};

// ---------------- DSMEM / sync helpers ----------------
__device__ __forceinline__ uint32_t smem_addr_u32(const void* p) {
    return (uint32_t)__cvta_generic_to_shared(p);
}
__device__ __forceinline__ uint32_t mapa_u32(uint32_t a, uint32_t rank) {
    uint32_t d;
    asm("mapa.shared::cluster.u32 %0, %1, %2;" : "=r"(d) : "r"(a), "r"(rank));
    return d;
}
__device__ __forceinline__ void st_remote_f32(uint32_t a, float v) {
    asm volatile("st.shared::cluster.f32 [%0], %1;" :: "r"(a), "f"(v) : "memory");
}
__device__ __forceinline__ void cluster_sync_all() {
    asm volatile("barrier.cluster.arrive.aligned;" ::: "memory");
    asm volatile("barrier.cluster.wait.aligned;" ::: "memory");
}
__device__ __forceinline__ void mbar_init(uint32_t a, uint32_t cnt) {
    asm volatile("mbarrier.inval.shared.b64 [%0];" :: "r"(a) : "memory");
    asm volatile("mbarrier.init.shared.b64 [%0], %1;" :: "r"(a), "r"(cnt) : "memory");
}
// remote arrive with release.cluster: orders this thread's prior st.shared::cluster
__device__ __forceinline__ void mbar_arrive_remote(uint32_t a) {
    asm volatile("mbarrier.arrive.release.cluster.shared::cluster.b64 _, [%0];"
                 :: "r"(a) : "memory");
}
__device__ __forceinline__ void mbar_wait(uint32_t a, uint32_t parity) {
    uint32_t done;
    asm volatile(
        "{\n\t.reg .pred p;\n\t"
        "mbarrier.try_wait.parity.acquire.cluster.shared::cta.b64 p, [%1], %2, 0x989680;\n\t"
        "selp.b32 %0, 1, 0, p;\n\t}"
        : "=r"(done) : "r"(a), "r"(parity) : "memory");
    while (!done) {
        asm volatile(
            "{\n\t.reg .pred p;\n\t"
            "mbarrier.try_wait.parity.acquire.cluster.shared::cta.b64 p, [%1], %2, 0x989680;\n\t"
            "selp.b32 %0, 1, 0, p;\n\t}"
            : "=r"(done) : "r"(a), "r"(parity) : "memory");
    }
}

// ---------------- math ----------------
typedef unsigned long long u64;

#define FMA2(d, a, b, c) \
    asm("fma.rn.f32x2 %0, %1, %2, %3;" : "=l"(d) : "l"(a), "l"(b), "l"(c))

__device__ __forceinline__ float hsum2(u64 a) {
    unsigned lo, hi;
    asm("mov.b64 {%0, %1}, %2;" : "=r"(lo), "=r"(hi) : "l"(a));
    return __uint_as_float(lo) + __uint_as_float(hi);
}

__device__ __forceinline__ float cfc_h(float a1, float a2, float aa, float ab) {
    float ff1 = tanhf(a1);
    float ff2 = tanhf(a2);
    float ti  = 0.5f * tanhf(0.5f * (aa + ab)) + 0.5f;   // sigmoid(aa+ab)
    return ff1 + ti * (ff2 - ff1);
}

// segmented matvec: 4 batch rows, k-packed f32x2.
// virtual k-range = [0, L1+L2); first RK floats of the WEIGHT row are register-cached.
// z segment 1: rows at z1 + r*S1, floats [0,L1); segment 2: z2 + r*S2, floats [0,L2).
template<int RK, int L1, int S1, int L2, int S2>
__device__ __forceinline__ void mvseg(const float* __restrict__ wsm,   // weights after RK
                                      const u64* __restrict__ wreg,
                                      const float* __restrict__ z1,
                                      const float* __restrict__ z2,
                                      float* __restrict__ o) {
    u64 a0 = 0, a1 = 0, a2 = 0, a3 = 0;
    #pragma unroll
    for (int k = 0; k < L1; k += 4) {
        u64 wx, wy;
        if (k + 4 <= RK) { wx = wreg[k / 2]; wy = wreg[k / 2 + 1]; }
        else { ulonglong2 wv = *(const ulonglong2*)(wsm + k - RK); wx = wv.x; wy = wv.y; }
        const float* z = z1 + k;
        ulonglong2 z0 = *(const ulonglong2*)(z + 0 * S1);
        ulonglong2 z1v = *(const ulonglong2*)(z + 1 * S1);
        ulonglong2 z2v = *(const ulonglong2*)(z + 2 * S1);
        ulonglong2 z3v = *(const ulonglong2*)(z + 3 * S1);
        FMA2(a0, wx, z0.x, a0); FMA2(a0, wy, z0.y, a0);
        FMA2(a1, wx, z1v.x, a1); FMA2(a1, wy, z1v.y, a1);
        FMA2(a2, wx, z2v.x, a2); FMA2(a2, wy, z2v.y, a2);
        FMA2(a3, wx, z3v.x, a3); FMA2(a3, wy, z3v.y, a3);
    }
    #pragma unroll
    for (int k2 = 0; k2 < L2; k2 += 4) {
        const int k = L1 + k2;
        u64 wx, wy;
        if (k + 4 <= RK) { wx = wreg[k / 2]; wy = wreg[k / 2 + 1]; }
        else { ulonglong2 wv = *(const ulonglong2*)(wsm + k - RK); wx = wv.x; wy = wv.y; }
        const float* z = z2 + k2;
        ulonglong2 z0 = *(const ulonglong2*)(z + 0 * S2);
        ulonglong2 z1v = *(const ulonglong2*)(z + 1 * S2);
        ulonglong2 z2v = *(const ulonglong2*)(z + 2 * S2);
        ulonglong2 z3v = *(const ulonglong2*)(z + 3 * S2);
        FMA2(a0, wx, z0.x, a0); FMA2(a0, wy, z0.y, a0);
        FMA2(a1, wx, z1v.x, a1); FMA2(a1, wy, z1v.y, a1);
        FMA2(a2, wx, z2v.x, a2); FMA2(a2, wy, z2v.y, a2);
        FMA2(a3, wx, z3v.x, a3); FMA2(a3, wy, z3v.y, a3);
    }
    o[0] = hsum2(a0); o[1] = hsum2(a1); o[2] = hsum2(a2); o[3] = hsum2(a3);
}

// ---------------- premask weights into SMEM (with virtual-column remap) ----------------
// MODE0 (layer0): v<141 -> v else pad.
// MODE1 (layer1): z = [input 77 | pad 3 | h 51 | pad 1]; v<77->v; 80<=v<131 -> v-3; else pad.
// MODE2 (layer2): z = [input 51 | pad 1 | h 128];        v<51->v; 52<=v<180 -> v-1; else pad.
template<int HLOC, int KP, int MODE, int KREAL>
__device__ void load_weights(float* sW, float* sB, const Params& p, int l, int rowoff, int tid) {
    const float* Ws[4] = { p.W1[l], p.W2[l], p.Wa[l], p.Wb[l] };
    const float* Bs[4] = { p.b1[l], p.b2[l], p.ba[l], p.bb[l] };
    const float* M = p.m[l];
    for (int mat = 0; mat < 4; ++mat) {
        const float* W = Ws[mat];
        for (int idx = tid; idx < HLOC * KP; idx += NT) {
            int j = idx / KP;
            int k = idx - j * KP;
            int src;
            if (MODE == 0)      src = (k < KREAL) ? k : -1;
            else if (MODE == 1) src = (k < 77) ? k : ((k >= 80 && k < 131) ? k - 3 : -1);
            else                src = (k < 51) ? k : ((k >= 52 && k < 180) ? k - 1 : -1);
            float v = 0.0f;
            if (src >= 0) {
                int gi = (rowoff + j) * KREAL + src;
                v = W[gi] * M[gi];
            }
            sW[mat * HLOC * KP + idx] = v;
        }
        for (int j = tid; j < HLOC; j += NT)
            sB[mat * HLOC + j] = Bs[mat][rowoff + j];
    }
}

// ---------------- stage 0: layer 0 ----------------
__device__ void run_stage0(const Params& p, int g, float* smf, uint32_t smu, int tid) {
    float* sW   = smf + STAGE_F;
    float* sB   = sW + 4 * H0 * KP0;
    float* sZ   = sB + 4 * H0;          // [x 64 | h 77 | pad 7] stride 148, 4 rows
    float* sAcc = sZ + 4 * KP0;         // 32 * 80

    load_weights<H0, KP0, 0, 141>(sW, sB, p, 0, 0, tid);
    for (int i = tid; i < 4 * KP0; i += NT) sZ[i] = 0.f;
    __syncthreads();
    for (int i = tid; i < 4 * H0; i += NT) {
        int r = i / H0, j = i - r * H0;
        sZ[r * KP0 + NF + j] = p.h0[(size_t)(g * 4 + r) * 256 + j];
    }
    const int xr2 = tid >> 6, xi = tid & 63;
    const float* xb = p.x + (size_t)(g * 4 + (xr2 & 3)) * NTIME * NF + xi;
    float xv = 0.f;
    if (tid < 256) {
        sZ[xr2 * KP0 + xi] = __ldg(xb);          // x(0)
        xv = __ldg(xb + NF);                     // x(1)
    }
    if (tid == 0)
        for (int s = 0; s < DEPTH; ++s) mbar_init(smu + MBA(s), 1);   // empty01
    __syncthreads();
    cluster_sync_all();

    // unit mapping
    const int uhalf = (tid >= 308);
    const int urow  = uhalf ? tid - 308 : tid;
    const int um    = urow / H0, uj = urow - um * H0;
    const float* wb = sW + urow * KP0 + (uhalf ? KA0 : 0);
    u64 wreg[RKC / 2];
    #pragma unroll
    for (int c = 0; c < RKC / 2; ++c) wreg[c] = *(const u64*)(wb + 2 * c);
    const float* wsm = wb + RKC;
    const int has_extra = (tid < 104);
    const int xrow = 204 + tid;
    const int xm = has_extra ? xrow / H0 : 0;
    const int xj = has_extra ? xrow - xm * H0 : 0;
    const float* wsx = sW + xrow * KP0 + KA0;
    const int er = (tid < 308) ? tid / H0 : 0;
    const int ej = (tid < 308) ? tid - er * H0 : 0;

    const uint32_t r1base = mapa_u32(smu, 1);

    for (int t = 0; t < NTIME; ++t) {
        __syncthreads();                                   // barrier1
        {
            float o[4];
            if (!uhalf) mvseg<RKC, KA0, KP0, 0, KP0>(wsm, wreg, sZ, sZ, o);
            else        mvseg<RKC, KB0, KP0, 0, KP0>(wsm, wreg, sZ + KA0, sZ, o);
            #pragma unroll
            for (int r = 0; r < 4; ++r) sAcc[(uhalf * 16 + um * 4 + r) * 80 + uj] = o[r];
            if (has_extra) {
                float ox[4];
                mvseg<0, KB0, KP0, 0, KP0>(wsx, nullptr, sZ + KA0, sZ, ox);
                #pragma unroll
                for (int r = 0; r < 4; ++r) sAcc[(16 + xm * 4 + r) * 80 + xj] = ox[r];
            }
        }
        __syncthreads();                                   // barrier2
        const int s = t & 7;
        if (tid < 308) {
            float v[4];
            #pragma unroll
            for (int m = 0; m < 4; ++m)
                v[m] = sAcc[(m * 4 + er) * 80 + ej] + sAcc[(16 + m * 4 + er) * 80 + ej]
                     + sB[m * H0 + ej];
            float h = cfc_h(v[0], v[1], v[2], v[3]);
            sZ[er * KP0 + NF + ej] = h;
            if (t >= DEPTH) mbar_wait(smu + MBA(s), ((t >> 3) - 1) & 1);   // empty01
            st_remote_f32(r1base + RING_BYTE + (uint32_t)(((s * 320) + er * 80 + ej) * 4), h);
            mbar_arrive_remote(r1base + MBA(s));                            // full01
        }
        if (tid < 256 && t + 1 < NTIME) {
            sZ[xr2 * KP0 + xi] = xv;                       // x(t+1)
            if (t + 2 < NTIME) xv = __ldg(xb + (size_t)(t + 2) * NF);
        }
    }
    if (p.out_size >= NB * NTIME * 128 + NB * 256 && tid < 308) {
        float* hx = p.out + (size_t)NB * NTIME * 128;
        hx[(size_t)(g * 4 + er) * 256 + ej] = sZ[er * KP0 + NF + ej];
    }
}

// ---------------- stage 1: layer 1 ----------------
__device__ void run_stage1(const Params& p, int g, float* smf, uint32_t smu, int tid) {
    float* sW   = smf + STAGE_F;
    float* sB   = sW + 4 * H1 * KP1;
    float* sZh  = sB + 4 * H1;          // own h: stride 52 (51 + 1 pad), 4 rows
    float* sAcc = sZh + 4 * 52;         // 32 * 56
    float* ring01 = smf + 128;          // byte 512, DEPTH * 320 floats

    load_weights<H1, KP1, 1, 128>(sW, sB, p, 1, 0, tid);
    for (int i = tid; i < 4 * 52; i += NT) sZh[i] = 0.f;
    for (int i = tid; i < DEPTH * 320; i += NT) ring01[i] = 0.f;
    __syncthreads();
    for (int i = tid; i < 4 * H1; i += NT) {
        int r = i / H1, j = i - r * H1;
        sZh[r * 52 + j] = p.h0[(size_t)(g * 4 + r) * 256 + H0 + j];
    }
    if (tid == 0) {
        for (int s = 0; s < DEPTH; ++s) mbar_init(smu + MBA(s), 308);  // full01
        for (int s = 0; s < DEPTH; ++s) mbar_init(smu + MBB(s), 2);    // empty12
    }
    __syncthreads();
    cluster_sync_all();

    const int has_unit = (tid < 408);
    const int uhalf = (tid >= 204);
    const int urow  = has_unit ? (uhalf ? tid - 204 : tid) : 0;
    const int um    = urow / H1, uj = urow - um * H1;
    const float* wb = sW + urow * KP1 + (uhalf ? 68 : 0);
    u64 wreg[RKC / 2];
    #pragma unroll
    for (int c = 0; c < RKC / 2; ++c) wreg[c] = *(const u64*)(wb + 2 * c);
    const float* wsm = wb + RKC;
    const int er = (tid < 204) ? tid / H1 : 0;
    const int ej = (tid < 204) ? tid - er * H1 : 0;

    const uint32_t r0base = mapa_u32(smu, 0);
    const uint32_t r2base = mapa_u32(smu, 2);
    const uint32_t r3base = mapa_u32(smu, 3);

    for (int t = 0; t < NTIME; ++t) {
        const int s = t & 7;
        mbar_wait(smu + MBA(s), (t >> 3) & 1);             // full01 (all threads read ring)
        __syncthreads();                                   // barrier1
        {
            const float* zr = ring01 + s * 320;
            if (has_unit) {
                float o[4];
                if (!uhalf) mvseg<RKC, 68, 80, 0, 52>(wsm, wreg, zr, sZh, o);
                else        mvseg<RKC, 12, 80, 52, 52>(wsm, wreg, zr + 68, sZh, o);
                #pragma unroll
                for (int r = 0; r < 4; ++r) sAcc[(uhalf * 16 + um * 4 + r) * 56 + uj] = o[r];
            }
        }
        __syncthreads();                                   // barrier2
        if (tid == 0) mbar_arrive_remote(r0base + MBA(s)); // empty01: slot consumed
        if (tid < 204) {
            float v[4];
            #pragma unroll
            for (int m = 0; m < 4; ++m)
                v[m] = sAcc[(m * 4 + er) * 56 + ej] + sAcc[(16 + m * 4 + er) * 56 + ej]
                     + sB[m * H1 + ej];
            float h = cfc_h(v[0], v[1], v[2], v[3]);
            sZh[er * 52 + ej] = h;
            if (t >= DEPTH) mbar_wait(smu + MBB(s), ((t >> 3) - 1) & 1);   // empty12
            uint32_t off = RING_BYTE + (uint32_t)(((s * 224) + er * 56 + ej) * 4);
            st_remote_f32(r2base + off, h);
            st_remote_f32(r3base + off, h);
            mbar_arrive_remote(r2base + MBA(s));           // full12 in rank2
            mbar_arrive_remote(r3base + MBA(s));           // full12 in rank3
        }
    }
    if (p.out_size >= NB * NTIME * 128 + NB * 256 && tid < 204) {
        float* hx = p.out + (size_t)NB * NTIME * 128;
        hx[(size_t)(g * 4 + er) * 256 + H0 + ej] = sZh[er * 52 + ej];
    }
}

// ---------------- stage 2: layer 2 half ----------------
template<int HALF>
__device__ void run_stage2(const Params& p, int g, float* smf, uint32_t smu, int tid) {
    float* sW   = smf + STAGE_F;
    float* sB   = sW + 4 * H2H * KP2;
    float* sZh  = sB + 4 * H2H;         // own h: stride 64, 4 rows
    float* sAcc = sZh + 4 * 64;         // 32 * 64
    float* ring12   = smf + 128;                  // DEPTH * 224 floats
    float* ringPeer = smf + 128 + DEPTH * 224;    // DEPTH * 256 floats

    const int peer_rank = HALF ? 2 : 3;

    load_weights<H2H, KP2, 2, 179>(sW, sB, p, 2, HALF * 64, tid);
    for (int i = tid; i < 4 * 64; i += NT) sZh[i] = 0.f;
    for (int i = tid; i < DEPTH * 224; i += NT) ring12[i] = 0.f;
    for (int i = tid; i < DEPTH * 256; i += NT) ringPeer[i] = 0.f;
    __syncthreads();
    for (int i = tid; i < 4 * 64; i += NT) {
        int r = i >> 6, j = i & 63;
        sZh[i] = p.h0[(size_t)(g * 4 + r) * 256 + 128 + HALF * 64 + j];
        // prefill peer slot 7 with peer half of h0 (read at t=0)
        ringPeer[7 * 256 + i] = p.h0[(size_t)(g * 4 + r) * 256 + 128 + (1 - HALF) * 64 + j];
    }
    if (tid == 0) {
        for (int s = 0; s < DEPTH; ++s) mbar_init(smu + MBA(s), 204);  // full12
        for (int s = 0; s < DEPTH; ++s) mbar_init(smu + MBB(s), 256);  // fullP
        for (int s = 0; s < DEPTH; ++s) mbar_init(smu + MBC(s), 1);    // emptyP
    }
    __syncthreads();
    cluster_sync_all();

    const int uhalf = tid >> 8;                   // 0: k[0,92), 1: k[92,180)
    const int urow  = tid & 255;
    const int um    = urow >> 6, uj = urow & 63;
    const float* wb = sW + urow * KP2 + (uhalf ? 92 : 0);
    u64 wreg[RKC / 2];
    #pragma unroll
    for (int c = 0; c < RKC / 2; ++c) wreg[c] = *(const u64*)(wb + 2 * c);
    const float* wsm = wb + RKC;
    const int r2 = (tid & 255) >> 6, j2 = tid & 63;

    const uint32_t r1base = mapa_u32(smu, 1);
    const uint32_t prbase = mapa_u32(smu, (uint32_t)peer_rank);

    for (int t = 0; t < NTIME; ++t) {
        const int s  = t & 7;
        const int sP = (t - 1) & 7;
        if (uhalf == 0) mbar_wait(smu + MBA(s), (t >> 3) & 1);               // full12
        if ((HALF == 1 || uhalf == 1) && t >= 1)
            mbar_wait(smu + MBB(sP), ((t - 1) >> 3) & 1);                    // fullP
        __syncthreads();                                   // barrier1
        {
            const float* zr12 = ring12 + s * 224;
            const float* zrP  = ringPeer + sP * 256;
            float o[4];
            if (HALF == 0) {
                if (!uhalf) mvseg<RKC, 52, 56, 40, 64>(wsm, wreg, zr12, sZh, o);
                else        mvseg<RKC, 24, 64, 64, 64>(wsm, wreg, sZh + 40, zrP, o);
            } else {
                if (!uhalf) mvseg<RKC, 52, 56, 40, 64>(wsm, wreg, zr12, zrP, o);
                else        mvseg<RKC, 24, 64, 64, 64>(wsm, wreg, zrP + 40, sZh, o);
            }
            #pragma unroll
            for (int r = 0; r < 4; ++r) sAcc[(uhalf * 16 + um * 4 + r) * 64 + uj] = o[r];
        }
        __syncthreads();                                   // barrier2
        if (tid == 0) {
            mbar_arrive_remote(r1base + MBB(s));           // empty12 in rank1
            if (t >= 1) mbar_arrive_remote(prbase + MBC(sP)); // peer.emptyP: peer slot consumed
        }
        if (tid < 256) {
            float v[4];
            #pragma unroll
            for (int m = 0; m < 4; ++m)
                v[m] = sAcc[(m * 4 + r2) * 64 + j2] + sAcc[(16 + m * 4 + r2) * 64 + j2]
                     + sB[m * H2H + j2];
            float h = cfc_h(v[0], v[1], v[2], v[3]);
            sZh[r2 * 64 + j2] = h;
            if (t >= DEPTH) mbar_wait(smu + MBC(s), ((t >> 3) - 1) & 1);     // emptyP
            st_remote_f32(prbase + RINGP_BYTE + (uint32_t)(((s * 256) + r2 * 64 + j2) * 4), h);
            mbar_arrive_remote(prbase + MBB(s));           // peer.fullP
            p.out[((size_t)(g * 4 + r2) * NTIME + t) * 128 + HALF * 64 + j2] = h;
        }
    }
    if (p.out_size >= NB * NTIME * 128 + NB * 256 && tid < 256) {
        float* hx = p.out + (size_t)NB * NTIME * 128;
        hx[(size_t)(g * 4 + r2) * 256 + 128 + HALF * 64 + j2] = sZh[r2 * 64 + j2];
    }
}

// ---------------- kernel ----------------
__global__ void __launch_bounds__(NT, 1) cfc_kernel(Params p) {
    extern __shared__ unsigned char smraw[];
    float* smf = (float*)smraw;
    const uint32_t smu = smem_addr_u32(smraw);
    const int stage = blockIdx.x & 3;
    const int g     = blockIdx.x >> 2;
    const int tid   = threadIdx.x;

    if      (stage == 0) run_stage0(p, g, smf, smu, tid);
    else if (stage == 1) run_stage1(p, g, smf, smu, tid);
    else if (stage == 2) run_stage2<0>(p, g, smf, smu, tid);
    else                 run_stage2<1>(p, g, smf, smu, tid);

    cluster_sync_all();   // no CTA exits while peers may still push into its smem
}

// ---------------- host launch ----------------
extern "C" void kernel_launch(void* const* d_in, const int* in_sizes, int n_in,
                              void* d_out, int out_size) {
    Params p;
    p.x  = (const float*)d_in[0];
    p.h0 = (const float*)d_in[1];
    bool sig_order = (n_in > 4 && in_sizes[4] == 77);
    for (int l = 0; l < 3; ++l) {
        int b = 2 + 9 * l;
        p.m[l] = (const float*)d_in[b];
        if (!sig_order) {
            p.W1[l] = (const float*)d_in[b + 1];
            p.W2[l] = (const float*)d_in[b + 2];
            p.Wa[l] = (const float*)d_in[b + 3];
            p.Wb[l] = (const float*)d_in[b + 4];
            p.b1[l] = (const float*)d_in[b + 5];
            p.b2[l] = (const float*)d_in[b + 6];
            p.ba[l] = (const float*)d_in[b + 7];
            p.bb[l] = (const float*)d_in[b + 8];
        } else {
            p.W1[l] = (const float*)d_in[b + 1];
            p.b1[l] = (const float*)d_in[b + 2];
            p.W2[l] = (const float*)d_in[b + 3];
            p.b2[l] = (const float*)d_in[b + 4];
            p.Wa[l] = (const float*)d_in[b + 5];
            p.ba[l] = (const float*)d_in[b + 6];
            p.Wb[l] = (const float*)d_in[b + 7];
            p.bb[l] = (const float*)d_in[b + 8];
        }
    }
    p.out = (float*)d_out;
    p.out_size = out_size;

    cudaFuncSetAttribute(cfc_kernel, cudaFuncAttributeMaxDynamicSharedMemorySize, SMEM_BYTES);

    cudaLaunchConfig_t cfg = {};
    cfg.gridDim  = dim3(4 * NG, 1, 1);
    cfg.blockDim = dim3(NT, 1, 1);
    cfg.dynamicSmemBytes = SMEM_BYTES;
    cfg.stream = 0;
    cudaLaunchAttribute attr[1];
    attr[0].id = cudaLaunchAttributeClusterDimension;
    attr[0].val.clusterDim.x = 4;
    attr[0].val.clusterDim.y = 1;
    attr[0].val.clusterDim.z = 1;
    cfg.attrs = attr;
    cfg.numAttrs = 1;
    cudaLaunchKernelEx(&cfg, cfc_kernel, p);
}